// round 2
// baseline (speedup 1.0000x reference)
#include <cuda_runtime.h>
#include <math.h>

#define NQ 4
#define NL 3
#define DIM 16

// Fixed 16x16 complex unitary for the params-only part of the circuit,
// packed row-major as (re, im) pairs: g_U[i*16 + j].
__device__ float2 g_U[DIM * DIM];

// ---------------------------------------------------------------------------
// Prekernel: simulate the params circuit on each of the 16 basis states to
// build column j of U. 16 threads, negligible cost.
// ---------------------------------------------------------------------------
__global__ void precompute_U_kernel(const float* __restrict__ params) {
    int j = threadIdx.x;
    if (j >= DIM) return;

    float2 a[DIM];
#pragma unroll
    for (int k = 0; k < DIM; k++) a[k] = make_float2(k == j ? 1.0f : 0.0f, 0.0f);

    for (int l = 0; l < NL; l++) {
        for (int w = 0; w < NQ; w++) {
            // RY(params[l,w,0])
            float ty = 0.5f * params[(l * NQ + w) * 2 + 0];
            float sy, cy;
            sincosf(ty, &sy, &cy);
            int m = 1 << (3 - w);
            for (int i = 0; i < DIM; i++) {
                if (!(i & m)) {
                    float2 a0 = a[i], a1 = a[i | m];
                    a[i]     = make_float2(cy * a0.x - sy * a1.x, cy * a0.y - sy * a1.y);
                    a[i | m] = make_float2(sy * a0.x + cy * a1.x, sy * a0.y + cy * a1.y);
                }
            }
            // RZ(params[l,w,1]): diag(e^{-it/2}, e^{+it/2})
            float tz = 0.5f * params[(l * NQ + w) * 2 + 1];
            float sz, cz;
            sincosf(tz, &sz, &cz);
            for (int i = 0; i < DIM; i++) {
                float2 v = a[i];
                if (i & m) a[i] = make_float2(cz * v.x - sz * v.y, cz * v.y + sz * v.x);
                else       a[i] = make_float2(cz * v.x + sz * v.y, cz * v.y - sz * v.x);
            }
        }
        // CNOT chain: control w, target w+1 -> swap target bit where control=1
        for (int w = 0; w < NQ - 1; w++) {
            int mc = 1 << (3 - w);
            int mt = 1 << (2 - w);
            for (int i = 0; i < DIM; i++) {
                if ((i & mc) && !(i & mt)) {
                    float2 t = a[i];
                    a[i] = a[i | mt];
                    a[i | mt] = t;
                }
            }
        }
    }

#pragma unroll
    for (int i = 0; i < DIM; i++) g_U[i * DIM + j] = a[i];
}

// ---------------------------------------------------------------------------
// Packed f32x2 helpers (ptxas never auto-fuses -> inline PTX)
// ---------------------------------------------------------------------------
__device__ __forceinline__ unsigned long long ffma2(unsigned long long a,
                                                    unsigned long long b,
                                                    unsigned long long c) {
    unsigned long long d;
    asm("fma.rn.f32x2 %0, %1, %2, %3;" : "=l"(d) : "l"(a), "l"(b), "l"(c));
    return d;
}

__device__ __forceinline__ unsigned long long pack2(float lo, float hi) {
    unsigned long long d;
    asm("mov.b64 %0, {%1, %2};" : "=l"(d) : "f"(lo), "f"(hi));
    return d;
}

__device__ __forceinline__ void unpack2(unsigned long long v, float& lo, float& hi) {
    asm("mov.b64 {%0, %1}, %2;" : "=f"(lo), "=f"(hi) : "l"(v));
}

// ---------------------------------------------------------------------------
// Main kernel: one item per thread.
//   s[16]   = product state from patch angles (real)
//   v       = U * s           (256 packed f32x2 FMAs)
//   p_i     = |v_i|^2
//   ev_w    = sum_i (+/-) p_i
// ---------------------------------------------------------------------------
__global__ __launch_bounds__(256) void vqc_main_kernel(
    const float4* __restrict__ patch, float4* __restrict__ out, int n) {
    __shared__ __align__(16) unsigned long long sU[DIM * DIM];

    int t = threadIdx.x;
    // stage U into shared (256 threads load 256 complex entries)
    {
        float2 u = g_U[t];
        sU[t] = pack2(u.x, u.y);
    }
    __syncthreads();

    int gid = blockIdx.x * 256 + t;
    if (gid >= n) return;

    float4 p = patch[gid];
    float s0, c0, s1, c1, s2, c2, s3, c3;
    __sincosf(0.5f * p.x, &s0, &c0);
    __sincosf(0.5f * p.y, &s1, &c1);
    __sincosf(0.5f * p.z, &s2, &c2);
    __sincosf(0.5f * p.w, &s3, &c3);

    float qa[4] = {c0 * c1, c0 * s1, s0 * c1, s0 * s1};
    float qb[4] = {c2 * c3, c2 * s3, s2 * c3, s2 * s3};

    // s broadcast into both halves of an f32x2 for packed complex-scale
    unsigned long long sp[DIM];
#pragma unroll
    for (int i = 0; i < DIM; i++) {
        float v = qa[i >> 2] * qb[i & 3];
        sp[i] = pack2(v, v);
    }

    const ulonglong2* U2 = reinterpret_cast<const ulonglong2*>(sU);

    float ev0 = 0.0f, ev1 = 0.0f, ev2 = 0.0f, ev3 = 0.0f;
#pragma unroll
    for (int i = 0; i < DIM; i++) {
        unsigned long long acc = 0ull;  // packed (0.0f, 0.0f)
#pragma unroll
        for (int jj = 0; jj < 8; jj++) {
            ulonglong2 uu = U2[i * 8 + jj];  // broadcast LDS.128: 2 complex entries
            acc = ffma2(uu.x, sp[2 * jj + 0], acc);
            acc = ffma2(uu.y, sp[2 * jj + 1], acc);
        }
        float vr, vi;
        unpack2(acc, vr, vi);
        float pr = fmaf(vr, vr, vi * vi);
        // <Z_w>: + if bit w of i is 0, - if 1  (bit w = (i >> (3-w)) & 1)
        ev0 = fmaf(pr, ((i >> 3) & 1) ? -1.0f : 1.0f, ev0);
        ev1 = fmaf(pr, ((i >> 2) & 1) ? -1.0f : 1.0f, ev1);
        ev2 = fmaf(pr, ((i >> 1) & 1) ? -1.0f : 1.0f, ev2);
        ev3 = fmaf(pr, ((i >> 0) & 1) ? -1.0f : 1.0f, ev3);
    }

    out[gid] = make_float4(ev0, ev1, ev2, ev3);
}

// ---------------------------------------------------------------------------
extern "C" void kernel_launch(void* const* d_in, const int* in_sizes, int n_in,
                              void* d_out, int out_size) {
    const float* patch  = (const float*)d_in[0];   // (B, 4) float32
    const float* params = (const float*)d_in[1];   // (3, 4, 2) float32
    int n = in_sizes[0] / 4;                       // B

    precompute_U_kernel<<<1, DIM>>>(params);

    int blocks = (n + 255) / 256;
    vqc_main_kernel<<<blocks, 256>>>(
        (const float4*)patch, (float4*)d_out, n);
}

// round 3
// speedup vs baseline: 1.0007x; 1.0007x over previous
#include <cuda_runtime.h>
#include <math.h>

#define NQ 4
#define NL 3
#define DIM 16

// Fixed 16x16 complex unitary for the params-only part of the circuit,
// packed row-major as (re, im) pairs: g_U[i*16 + j].
__device__ float2 g_U[DIM * DIM];

// ---------------------------------------------------------------------------
// Prekernel: simulate the params circuit on each of the 16 basis states to
// build column j of U. 16 threads, negligible cost.
// ---------------------------------------------------------------------------
__global__ void precompute_U_kernel(const float* __restrict__ params) {
    int j = threadIdx.x;
    if (j >= DIM) return;

    float2 a[DIM];
#pragma unroll
    for (int k = 0; k < DIM; k++) a[k] = make_float2(k == j ? 1.0f : 0.0f, 0.0f);

    for (int l = 0; l < NL; l++) {
        for (int w = 0; w < NQ; w++) {
            // RY(params[l,w,0])
            float ty = 0.5f * params[(l * NQ + w) * 2 + 0];
            float sy, cy;
            sincosf(ty, &sy, &cy);
            int m = 1 << (3 - w);
            for (int i = 0; i < DIM; i++) {
                if (!(i & m)) {
                    float2 a0 = a[i], a1 = a[i | m];
                    a[i]     = make_float2(cy * a0.x - sy * a1.x, cy * a0.y - sy * a1.y);
                    a[i | m] = make_float2(sy * a0.x + cy * a1.x, sy * a0.y + cy * a1.y);
                }
            }
            // RZ(params[l,w,1]): diag(e^{-it/2}, e^{+it/2})
            float tz = 0.5f * params[(l * NQ + w) * 2 + 1];
            float sz, cz;
            sincosf(tz, &sz, &cz);
            for (int i = 0; i < DIM; i++) {
                float2 v = a[i];
                if (i & m) a[i] = make_float2(cz * v.x - sz * v.y, cz * v.y + sz * v.x);
                else       a[i] = make_float2(cz * v.x + sz * v.y, cz * v.y - sz * v.x);
            }
        }
        // CNOT chain: control w, target w+1 -> swap target bit where control=1
        for (int w = 0; w < NQ - 1; w++) {
            int mc = 1 << (3 - w);
            int mt = 1 << (2 - w);
            for (int i = 0; i < DIM; i++) {
                if ((i & mc) && !(i & mt)) {
                    float2 t = a[i];
                    a[i] = a[i | mt];
                    a[i | mt] = t;
                }
            }
        }
    }

#pragma unroll
    for (int i = 0; i < DIM; i++) g_U[i * DIM + j] = a[i];
}

// ---------------------------------------------------------------------------
// Packed f32x2 helpers (ptxas never auto-fuses -> inline PTX)
// ---------------------------------------------------------------------------
__device__ __forceinline__ unsigned long long ffma2(unsigned long long a,
                                                    unsigned long long b,
                                                    unsigned long long c) {
    unsigned long long d;
    asm("fma.rn.f32x2 %0, %1, %2, %3;" : "=l"(d) : "l"(a), "l"(b), "l"(c));
    return d;
}

__device__ __forceinline__ unsigned long long pack2(float lo, float hi) {
    unsigned long long d;
    asm("mov.b64 %0, {%1, %2};" : "=l"(d) : "f"(lo), "f"(hi));
    return d;
}

__device__ __forceinline__ void unpack2(unsigned long long v, float& lo, float& hi) {
    asm("mov.b64 {%0, %1}, %2;" : "=f"(lo), "=f"(hi) : "l"(v));
}

// ---------------------------------------------------------------------------
// Main kernel: one item per thread.
//   s[16]   = product state from patch angles (real)
//   v       = U * s           (256 packed f32x2 FMAs)
//   p_i     = |v_i|^2
//   ev_w    = sum_i (+/-) p_i
// ---------------------------------------------------------------------------
__global__ __launch_bounds__(256) void vqc_main_kernel(
    const float4* __restrict__ patch, float4* __restrict__ out, int n) {
    __shared__ __align__(16) unsigned long long sU[DIM * DIM];

    int t = threadIdx.x;
    // stage U into shared (256 threads load 256 complex entries)
    {
        float2 u = g_U[t];
        sU[t] = pack2(u.x, u.y);
    }
    __syncthreads();

    int gid = blockIdx.x * 256 + t;
    if (gid >= n) return;

    float4 p = patch[gid];
    float s0, c0, s1, c1, s2, c2, s3, c3;
    __sincosf(0.5f * p.x, &s0, &c0);
    __sincosf(0.5f * p.y, &s1, &c1);
    __sincosf(0.5f * p.z, &s2, &c2);
    __sincosf(0.5f * p.w, &s3, &c3);

    float qa[4] = {c0 * c1, c0 * s1, s0 * c1, s0 * s1};
    float qb[4] = {c2 * c3, c2 * s3, s2 * c3, s2 * s3};

    // s broadcast into both halves of an f32x2 for packed complex-scale
    unsigned long long sp[DIM];
#pragma unroll
    for (int i = 0; i < DIM; i++) {
        float v = qa[i >> 2] * qb[i & 3];
        sp[i] = pack2(v, v);
    }

    const ulonglong2* U2 = reinterpret_cast<const ulonglong2*>(sU);

    float ev0 = 0.0f, ev1 = 0.0f, ev2 = 0.0f, ev3 = 0.0f;
#pragma unroll
    for (int i = 0; i < DIM; i++) {
        unsigned long long acc = 0ull;  // packed (0.0f, 0.0f)
#pragma unroll
        for (int jj = 0; jj < 8; jj++) {
            ulonglong2 uu = U2[i * 8 + jj];  // broadcast LDS.128: 2 complex entries
            acc = ffma2(uu.x, sp[2 * jj + 0], acc);
            acc = ffma2(uu.y, sp[2 * jj + 1], acc);
        }
        float vr, vi;
        unpack2(acc, vr, vi);
        float pr = fmaf(vr, vr, vi * vi);
        // <Z_w>: + if bit w of i is 0, - if 1  (bit w = (i >> (3-w)) & 1)
        ev0 = fmaf(pr, ((i >> 3) & 1) ? -1.0f : 1.0f, ev0);
        ev1 = fmaf(pr, ((i >> 2) & 1) ? -1.0f : 1.0f, ev1);
        ev2 = fmaf(pr, ((i >> 1) & 1) ? -1.0f : 1.0f, ev2);
        ev3 = fmaf(pr, ((i >> 0) & 1) ? -1.0f : 1.0f, ev3);
    }

    out[gid] = make_float4(ev0, ev1, ev2, ev3);
}

// ---------------------------------------------------------------------------
extern "C" void kernel_launch(void* const* d_in, const int* in_sizes, int n_in,
                              void* d_out, int out_size) {
    const float* patch  = (const float*)d_in[0];   // (B, 4) float32
    const float* params = (const float*)d_in[1];   // (3, 4, 2) float32
    int n = in_sizes[0] / 4;                       // B

    precompute_U_kernel<<<1, DIM>>>(params);

    int blocks = (n + 255) / 256;
    vqc_main_kernel<<<blocks, 256>>>(
        (const float4*)patch, (float4*)d_out, n);
}

// round 4
// speedup vs baseline: 1.1493x; 1.1485x over previous
#include <cuda_runtime.h>
#include <math.h>

#define NQ 4
#define NL 3
#define DIM 16

// Fixed 16x16 complex unitary for the params-only part of the circuit,
// packed row-major as (re, im) pairs: g_U[i*16 + j].
__device__ float2 g_U[DIM * DIM];

// ---------------------------------------------------------------------------
// Prekernel: simulate the params circuit on each of the 16 basis states to
// build column j of U. 16 threads, negligible cost.
// ---------------------------------------------------------------------------
__global__ void precompute_U_kernel(const float* __restrict__ params) {
    int j = threadIdx.x;
    if (j >= DIM) return;

    float2 a[DIM];
#pragma unroll
    for (int k = 0; k < DIM; k++) a[k] = make_float2(k == j ? 1.0f : 0.0f, 0.0f);

    for (int l = 0; l < NL; l++) {
        for (int w = 0; w < NQ; w++) {
            float ty = 0.5f * params[(l * NQ + w) * 2 + 0];
            float sy, cy;
            sincosf(ty, &sy, &cy);
            int m = 1 << (3 - w);
            for (int i = 0; i < DIM; i++) {
                if (!(i & m)) {
                    float2 a0 = a[i], a1 = a[i | m];
                    a[i]     = make_float2(cy * a0.x - sy * a1.x, cy * a0.y - sy * a1.y);
                    a[i | m] = make_float2(sy * a0.x + cy * a1.x, sy * a0.y + cy * a1.y);
                }
            }
            float tz = 0.5f * params[(l * NQ + w) * 2 + 1];
            float sz, cz;
            sincosf(tz, &sz, &cz);
            for (int i = 0; i < DIM; i++) {
                float2 v = a[i];
                if (i & m) a[i] = make_float2(cz * v.x - sz * v.y, cz * v.y + sz * v.x);
                else       a[i] = make_float2(cz * v.x + sz * v.y, cz * v.y - sz * v.x);
            }
        }
        for (int w = 0; w < NQ - 1; w++) {
            int mc = 1 << (3 - w);
            int mt = 1 << (2 - w);
            for (int i = 0; i < DIM; i++) {
                if ((i & mc) && !(i & mt)) {
                    float2 t = a[i];
                    a[i] = a[i | mt];
                    a[i | mt] = t;
                }
            }
        }
    }

#pragma unroll
    for (int i = 0; i < DIM; i++) g_U[i * DIM + j] = a[i];
}

// ---------------------------------------------------------------------------
// Packed f32x2 helpers (ptxas never auto-fuses -> inline PTX)
// ---------------------------------------------------------------------------
typedef unsigned long long u64;

__device__ __forceinline__ u64 ffma2(u64 a, u64 b, u64 c) {
    u64 d;
    asm("fma.rn.f32x2 %0, %1, %2, %3;" : "=l"(d) : "l"(a), "l"(b), "l"(c));
    return d;
}

__device__ __forceinline__ u64 fadd2(u64 a, u64 b) {
    u64 d;
    asm("add.rn.f32x2 %0, %1, %2;" : "=l"(d) : "l"(a), "l"(b));
    return d;
}

__device__ __forceinline__ u64 pack2(float lo, float hi) {
    u64 d;
    asm("mov.b64 %0, {%1, %2};" : "=l"(d) : "f"(lo), "f"(hi));
    return d;
}

__device__ __forceinline__ void unpack2(u64 v, float& lo, float& hi) {
    asm("mov.b64 {%0, %1}, %2;" : "=f"(lo), "=f"(hi) : "l"(v));
}

// ---------------------------------------------------------------------------
// Main kernel: TWO items per thread so every broadcast LDS.128 of a U-row
// chunk feeds 4 ffma2 (2 items x {re,im} pair) instead of 2.
// ---------------------------------------------------------------------------
__global__ __launch_bounds__(256) void vqc_main_kernel(
    const float4* __restrict__ patch, float4* __restrict__ out, int n) {
    __shared__ __align__(16) u64 sU[DIM * DIM];

    int t = threadIdx.x;
    {
        float2 u = g_U[t];
        sU[t] = pack2(u.x, u.y);
    }
    __syncthreads();

    int iA = blockIdx.x * 512 + t;
    int iB = iA + 256;
    bool vA = iA < n, vB = iB < n;
    int lA = vA ? iA : 0;
    int lB = vB ? iB : 0;

    float4 pA = patch[lA];
    float4 pB = patch[lB];

    // Build the two rank-1 product states (real), each entry duplicated
    // into both halves of an f32x2.
    u64 spA[DIM], spB[DIM];
    {
        float s0, c0, s1, c1, s2, c2, s3, c3;
        __sincosf(0.5f * pA.x, &s0, &c0);
        __sincosf(0.5f * pA.y, &s1, &c1);
        __sincosf(0.5f * pA.z, &s2, &c2);
        __sincosf(0.5f * pA.w, &s3, &c3);
        float qa[4] = {c0 * c1, c0 * s1, s0 * c1, s0 * s1};
        float qb[4] = {c2 * c3, c2 * s3, s2 * c3, s2 * s3};
#pragma unroll
        for (int i = 0; i < DIM; i++) {
            float v = qa[i >> 2] * qb[i & 3];
            spA[i] = pack2(v, v);
        }
    }
    {
        float s0, c0, s1, c1, s2, c2, s3, c3;
        __sincosf(0.5f * pB.x, &s0, &c0);
        __sincosf(0.5f * pB.y, &s1, &c1);
        __sincosf(0.5f * pB.z, &s2, &c2);
        __sincosf(0.5f * pB.w, &s3, &c3);
        float qa[4] = {c0 * c1, c0 * s1, s0 * c1, s0 * s1};
        float qb[4] = {c2 * c3, c2 * s3, s2 * c3, s2 * s3};
#pragma unroll
        for (int i = 0; i < DIM; i++) {
            float v = qa[i >> 2] * qb[i & 3];
            spB[i] = pack2(v, v);
        }
    }

    const ulonglong2* U2 = reinterpret_cast<const ulonglong2*>(sU);

    // Packed +/-1 sign pairs for the ev accumulation (hoisted, 4 u64).
    u64 sgn[4];
    sgn[0] = pack2( 1.0f,  1.0f);
    sgn[1] = pack2( 1.0f, -1.0f);
    sgn[2] = pack2(-1.0f,  1.0f);
    sgn[3] = pack2(-1.0f, -1.0f);

    u64 evA01 = 0ull, evA23 = 0ull, evB01 = 0ull, evB23 = 0ull;

#pragma unroll
    for (int i = 0; i < DIM; i++) {
        // two accumulator chains per item for ILP (8-deep instead of 16-deep)
        u64 aA0 = 0ull, aA1 = 0ull, aB0 = 0ull, aB1 = 0ull;
#pragma unroll
        for (int jj = 0; jj < 8; jj++) {
            ulonglong2 uu = U2[i * 8 + jj];  // broadcast LDS.128: 2 complex U entries
            aA0 = ffma2(uu.x, spA[2 * jj + 0], aA0);
            aA1 = ffma2(uu.y, spA[2 * jj + 1], aA1);
            aB0 = ffma2(uu.x, spB[2 * jj + 0], aB0);
            aB1 = ffma2(uu.y, spB[2 * jj + 1], aB1);
        }
        u64 aA = fadd2(aA0, aA1);
        u64 aB = fadd2(aB0, aB1);

        float vrA, viA, vrB, viB;
        unpack2(aA, vrA, viA);
        unpack2(aB, vrB, viB);
        float prA = fmaf(vrA, vrA, viA * viA);
        float prB = fmaf(vrB, vrB, viB * viB);
        u64 pAp = pack2(prA, prA);
        u64 pBp = pack2(prB, prB);

        // ev0 sign = bit3 of i, ev1 = bit2, ev2 = bit1, ev3 = bit0
        const int s01 = ((i >> 3) & 1) * 2 + ((i >> 2) & 1);
        const int s23 = ((i >> 1) & 1) * 2 + ((i >> 0) & 1);
        evA01 = ffma2(pAp, sgn[s01], evA01);
        evA23 = ffma2(pAp, sgn[s23], evA23);
        evB01 = ffma2(pBp, sgn[s01], evB01);
        evB23 = ffma2(pBp, sgn[s23], evB23);
    }

    float e0, e1, e2, e3;
    if (vA) {
        unpack2(evA01, e0, e1);
        unpack2(evA23, e2, e3);
        out[iA] = make_float4(e0, e1, e2, e3);
    }
    if (vB) {
        unpack2(evB01, e0, e1);
        unpack2(evB23, e2, e3);
        out[iB] = make_float4(e0, e1, e2, e3);
    }
}

// ---------------------------------------------------------------------------
extern "C" void kernel_launch(void* const* d_in, const int* in_sizes, int n_in,
                              void* d_out, int out_size) {
    const float* patch  = (const float*)d_in[0];   // (B, 4) float32
    const float* params = (const float*)d_in[1];   // (3, 4, 2) float32
    int n = in_sizes[0] / 4;                       // B

    precompute_U_kernel<<<1, DIM>>>(params);

    int blocks = (n + 511) / 512;
    vqc_main_kernel<<<blocks, 256>>>(
        (const float4*)patch, (float4*)d_out, n);
}